// round 16
// baseline (speedup 1.0000x reference)
#include <cuda_runtime.h>
#include <cstdint>

#define BB      1024
#define MAXLEN  200
#define FF      64
#define DD      64
#define NT      256
#define KT      (MAXLEN * DD)              // 12800 floats per k tile
#define KBYTES  (KT * 4)                   // 51200 bytes
// smem floats: 4 (mbar) + KT + spart 16*64 + su 64 + sub 64 + swr 16
#define SMEM2_FLOATS (4 + KT + 16 * DD + DD + DD + 16)
#define SMEM2_BYTES  (SMEM2_FLOATS * 4)    // 55,888 B -> 4 CTAs/SM

__device__ float g_u[BB * DD];             // 256 KB scratch: u per batch

__device__ __forceinline__ float fast_sigmoid(float x) {
    float t;
    asm("tanh.approx.f32 %0, %1;" : "=f"(t) : "f"(0.5f * x));
    return fmaf(0.5f, t, 0.5f);
}
__device__ __forceinline__ float fast_exp8(float x) {   // exp(x/8)
    float e;
    asm("ex2.approx.f32 %0, %1;" : "=f"(e) : "f"(x * 0.18033688011112042f));
    return e;
}
__device__ __forceinline__ void mbar_wait(uint32_t mbar, uint32_t parity) {
    uint32_t done = 0;
    while (!done) {
        asm volatile(
            "{\n\t.reg .pred p;\n\t"
            "mbarrier.try_wait.parity.shared::cta.b64 p, [%1], %2, 0x989680;\n\t"
            "selp.b32 %0, 1, 0, p;\n\t}"
            : "=r"(done) : "r"(mbar), "r"(parity) : "memory");
    }
}

// ================= Kernel 1: u[b] = ((fs.q[b]) @ Wq) @ Wk^T =================
__global__ __launch_bounds__(NT, 8)
void u_kernel(const float* __restrict__ q,
              const float* __restrict__ fs,
              const float* __restrict__ Wq,
              const float* __restrict__ Wk) {
    __shared__ float spart[16 * DD];
    __shared__ float squ[DD];
    __shared__ float stmp[DD];

    const int b   = blockIdx.x;
    const int tid = threadIdx.x;
    const int hw  = tid >> 4;
    const int l16 = tid & 15;

    // qbar[d] = sum_f fs[f] * q[b,f,d]
    {
        const float4* qb4 = (const float4*)(q + (size_t)b * FF * DD);
        float4 a = make_float4(0.f, 0.f, 0.f, 0.f);
#pragma unroll
        for (int fi = 0; fi < 4; ++fi) {
            int f = hw + 16 * fi;
            float s = fs[f];
            float4 v = qb4[f * 16 + l16];
            a.x += s * v.x; a.y += s * v.y; a.z += s * v.z; a.w += s * v.w;
        }
        ((float4*)spart)[hw * 16 + l16] = a;
    }
    __syncthreads();
    if (tid < DD) {
        float s = 0.f;
#pragma unroll
        for (int i = 0; i < 16; ++i) s += spart[i * DD + tid];
        squ[tid] = s;
    }
    __syncthreads();

    // tmp[e] = sum_c qbar[c] * Wq[c,e]
    {
        float4 a = make_float4(0.f, 0.f, 0.f, 0.f);
#pragma unroll
        for (int ci = 0; ci < 4; ++ci) {
            int c = hw * 4 + ci;
            float s = squ[c];
            float4 v = ((const float4*)Wq)[c * 16 + l16];
            a.x += s * v.x; a.y += s * v.y; a.z += s * v.z; a.w += s * v.w;
        }
        ((float4*)spart)[hw * 16 + l16] = a;
    }
    __syncthreads();
    if (tid < DD) {
        float s = 0.f;
#pragma unroll
        for (int i = 0; i < 16; ++i) s += spart[i * DD + tid];
        stmp[tid] = s;
    }
    __syncthreads();

    // u[row] = sum_e tmp[e] * Wk[row,e]
    {
        float4 tv = ((const float4*)stmp)[l16];
#pragma unroll
        for (int r = 0; r < 4; ++r) {
            int row = hw + 16 * r;
            float4 wv = ((const float4*)(Wk + row * DD))[l16];
            float p = wv.x * tv.x + wv.y * tv.y + wv.z * tv.z + wv.w * tv.w;
#pragma unroll
            for (int o = 8; o; o >>= 1)
                p += __shfl_xor_sync(0xffffffffu, p, o);
            if (l16 == 0) g_u[b * DD + row] = p;
        }
    }
}

// ==== Kernel 2: k via TMA bulk copy (UBLKCP) — bypass the L1TEX miss queue ====
__global__ __launch_bounds__(NT, 4)
void score_kernel(const float* __restrict__ k,
                  const int*   __restrict__ kes_length,
                  const float* __restrict__ bias,
                  const float* __restrict__ Wv,
                  float*       __restrict__ out) {
    extern __shared__ float smd[];
    // [0:16) mbarrier (+pad), [16:) kbuf, then reduction scratch
    uint32_t mbar = (uint32_t)__cvta_generic_to_shared(smd);
    float* kbuf  = smd + 4;                // 16B-aligned TMA destination
    float* spart = kbuf + KT;
    float* su    = spart + 16 * DD;
    float* sub   = su + DD;
    float* swr   = sub + DD;

    const int b   = blockIdx.x;
    const int tid = threadIdx.x;
    const int hw  = tid >> 4;              // half-warp id 0..15
    const int l16 = tid & 15;

    if (tid == 0)
        asm volatile("mbarrier.init.shared::cta.b64 [%0], %1;" :: "r"(mbar), "r"(1) : "memory");
    __syncthreads();                        // init visible CTA-wide before TMA

    if (tid == 0) {
        asm volatile("mbarrier.arrive.expect_tx.shared::cta.b64 _, [%0], %1;"
                     :: "r"(mbar), "r"((uint32_t)KBYTES) : "memory");
        asm volatile("cp.async.bulk.shared::cta.global.mbarrier::complete_tx::bytes "
                     "[%0], [%1], %2, [%3];"
                     :: "r"((uint32_t)__cvta_generic_to_shared(kbuf)),
                        "l"(k + (size_t)b * KT), "r"((uint32_t)KBYTES), "r"(mbar)
                     : "memory");
    }

    // tiny loads ride under the bulk copy
    if (tid < 16)
        ((float4*)sub)[tid] = ((const float4*)(g_u + (size_t)b * DD))[tid];
    const int   len   = kes_length[b];
    const float biasD = bias[0] * (float)DD;
    const float mfill = (len == 0) ? 1.f : 0.f;
    __syncthreads();                        // sub visible
    const float4 uv = ((const float4*)sub)[l16];

    mbar_wait(mbar, 0);                     // k tile landed

    // ---- fused score+weighted pass (half-warp per row) ----
    const float4* kt4 = (const float4*)kbuf;
    float4 wa   = make_float4(0.f, 0.f, 0.f, 0.f);
    float  esum = 0.f;
#pragma unroll
    for (int i = 0; i < 13; ++i) {
        int t = hw + (i << 4);
        if (t < MAXLEN) {
            float4 kv = kt4[t * 16 + l16];
            float p = kv.x * uv.x + kv.y * uv.y + kv.z * uv.z + kv.w * uv.w;
#pragma unroll
            for (int o = 8; o; o >>= 1)
                p += __shfl_xor_sync(0xffffffffu, p, o);   // 16-lane reduce
            float e = (t < len) ? fast_exp8(fast_sigmoid(p + biasD)) : mfill;
            wa.x += e * kv.x; wa.y += e * kv.y;
            wa.z += e * kv.z; wa.w += e * kv.w;
            esum += e;
        }
    }

    ((float4*)spart)[hw * 16 + l16] = wa;
    if (l16 == 0) swr[hw] = esum;
    __syncthreads();

    if (tid < DD) {
        float s = 0.f;
#pragma unroll
        for (int i = 0; i < 16; ++i) s += spart[i * DD + tid];
        su[tid] = s;
    }
    __syncthreads();

    // ---- out[b,e] = inv * sum_c w[c] * Wv[c,e] ----
    {
        float4 a = make_float4(0.f, 0.f, 0.f, 0.f);
#pragma unroll
        for (int ci = 0; ci < 4; ++ci) {
            int c = hw * 4 + ci;
            float s = su[c];
            float4 v = ((const float4*)Wv)[c * 16 + l16];
            a.x += s * v.x; a.y += s * v.y; a.z += s * v.z; a.w += s * v.w;
        }
        ((float4*)spart)[hw * 16 + l16] = a;
    }
    __syncthreads();
    if (tid < DD) {
        float tot = 0.f;
#pragma unroll
        for (int i = 0; i < 16; ++i) tot += swr[i];
        float s = 0.f;
#pragma unroll
        for (int i = 0; i < 16; ++i) s += spart[i * DD + tid];
        out[(size_t)b * DD + tid] = s * (1.f / tot);
    }
}

extern "C" void kernel_launch(void* const* d_in, const int* in_sizes, int n_in,
                              void* d_out, int out_size) {
    const float* q    = (const float*)d_in[0];
    const float* k    = (const float*)d_in[1];
    // d_in[2] = v : unused by the reference computation
    const int*   kes  = (const int*)  d_in[3];
    const float* fs   = (const float*)d_in[4];
    const float* bias = (const float*)d_in[5];
    const float* Wq   = (const float*)d_in[6];
    const float* Wk   = (const float*)d_in[7];
    const float* Wv   = (const float*)d_in[8];
    float*       out  = (float*)d_out;

    cudaFuncSetAttribute(score_kernel, cudaFuncAttributePreferredSharedMemoryCarveout, 100);
    cudaFuncSetAttribute(score_kernel, cudaFuncAttributeMaxDynamicSharedMemorySize, SMEM2_BYTES);

    u_kernel<<<BB, NT>>>(q, fs, Wq, Wk);
    score_kernel<<<BB, NT, SMEM2_BYTES>>>(k, kes, bias, Wv, out);
}